// round 4
// baseline (speedup 1.0000x reference)
#include <cuda_runtime.h>
#include <cstdint>

#define T_LEN 1000
#define B_SZ  512
#define C_IN  22
#define H_SZ  64
#define G4    256
#define BC    (B_SZ * C_IN)   // 11264
#define TH    (T_LEN * H_SZ)  // 64000

typedef unsigned long long ull;

// Scratch: x transposed to [t][b][c] (45 MB static device array)
__device__ float g_xT[T_LEN * BC];

// ---------------------------------------------------------------------------
// Kernel 1: transpose x [B*C, T] -> xT [T, B*C]
// ---------------------------------------------------------------------------
__global__ void transpose_kernel(const float* __restrict__ x) {
    __shared__ float tile[32][33];
    const int tx = threadIdx.x, ty = threadIdx.y;
    const int t0 = blockIdx.x * 32;
    const int r0 = blockIdx.y * 32;
#pragma unroll
    for (int i = 0; i < 32; i += 8) {
        int t = t0 + tx, r = r0 + ty + i;
        if (t < T_LEN) tile[ty + i][tx] = x[r * T_LEN + t];
    }
    __syncthreads();
#pragma unroll
    for (int i = 0; i < 32; i += 8) {
        int t = t0 + ty + i, r = r0 + tx;
        if (t < T_LEN) g_xT[t * BC + r] = tile[tx][ty + i];
    }
}

// ---------------------------------------------------------------------------
// helpers
// ---------------------------------------------------------------------------
__device__ __forceinline__ ull pack2f(float lo, float hi) {
    ull r;
    uint32_t a = __float_as_uint(lo), b = __float_as_uint(hi);
    asm("mov.b64 %0, {%1, %2};" : "=l"(r) : "r"(a), "r"(b));
    return r;
}
__device__ __forceinline__ void ffma2(ull& d, ull a, ull b) {
    asm("fma.rn.f32x2 %0, %1, %2, %3;" : "=l"(d) : "l"(a), "l"(b), "l"(d));
}
__device__ __forceinline__ ull add2(ull a, ull b) {
    ull r;
    asm("add.rn.f32x2 %0, %1, %2;" : "=l"(r) : "l"(a), "l"(b));
    return r;
}
__device__ __forceinline__ void unpack2(ull v, float& lo, float& hi) {
    uint32_t ulo, uhi;
    asm("mov.b64 {%0, %1}, %2;" : "=r"(ulo), "=r"(uhi) : "l"(v));
    lo = __uint_as_float(ulo);
    hi = __uint_as_float(uhi);
}
__device__ __forceinline__ float tanh_fast(float x) {
    float y;
    asm("tanh.approx.f32 %0, %1;" : "=f"(y) : "f"(x));
    return y;
}

// ---------------------------------------------------------------------------
// Kernel 2: fused LSTM + FC + softmax, software-pipelined over the CTA's
// two batch rows X (=r0) and Y (=r0+1).
//   I1: gates_X(t) [all 256 thr] + state_Y(t-1) [thr 64..127] + stage x_Y(t+1)
//   I2: gates_Y(t) [all 256 thr] + state_X(t)   [thr 0..63]   + stage x_X(t+1)
// Every barrier interval is FMA-dense; state-update latency is hidden.
// ---------------------------------------------------------------------------
__global__ void __launch_bounds__(256, 2) lstm_fused(
    const float* __restrict__ W_ih, const float* __restrict__ W_hh,
    const float* __restrict__ b_ih, const float* __restrict__ b_hh,
    const float* __restrict__ W_fc, const float* __restrict__ b_fc,
    float* __restrict__ out)
{
    __shared__ __align__(16) ull hX[32], hY[32];       // h, hidden-pair packed
    __shared__ __align__(16) ull xXs[2][12], xYs[2][12]; // x double-buffered
    __shared__ float gX[G4], gY[G4];                   // nonlinearized gates
    __shared__ float red[2 * 4 * 64];
    __shared__ float logits_sh[2][4];

    const int j  = threadIdx.x;            // gate column 0..255
    const int r0 = blockIdx.x * 2;

    // --- pack weights for gate column j (once) ---
    ull whhp[32];
    {
        const float4* wp = reinterpret_cast<const float4*>(W_hh + j * H_SZ);
#pragma unroll
        for (int k = 0; k < 16; k++) {
            float4 v = wp[k];
            whhp[2*k]   = pack2f(v.x, v.y);
            whhp[2*k+1] = pack2f(v.z, v.w);
        }
    }
    ull wihp[11];
    {
        const float2* wp = reinterpret_cast<const float2*>(W_ih + j * C_IN);
#pragma unroll
        for (int c = 0; c < 11; c++) {
            float2 v = wp[c];
            wihp[c] = pack2f(v.x, v.y);
        }
    }
    const float bias = b_ih[j] + b_hh[j];

    // nonlinearity for this column: g-gate (128..191) = tanh, else sigmoid
    const bool is_g  = ((j >> 6) == 2);
    const float nl_pre = is_g ? 1.f : 0.5f;
    const float nl_sc  = is_g ? 1.f : 0.5f;
    const float nl_off = is_g ? 0.f : 0.5f;

    // --- roles ---
    const int  hidx = j & 63;
    const bool isBX = (j < 64);                 // state thread, row X
    const bool isBY = (j >= 64 && j < 128);     // state thread, row Y
    const bool isSX = (j >= 128 && j < 150);    // x-stager, row X, channel j-128
    const bool isSY = (j >= 160 && j < 182);    // x-stager, row Y, channel j-160

    // init h = 0
    if (j < 32)            hX[j]      = 0ull;
    else if (j < 64)       hY[j - 32] = 0ull;

    // state-thread registers
    float c_state = 0.f;
    float p0 = 0.f, p1 = 0.f, p2 = 0.f, p3 = 0.f;
    float wf0 = 0.f, wf1 = 0.f, wf2 = 0.f, wf3 = 0.f;
    if (j < 128) {   // prefetch W_fc(t=0)
        const float* pf = W_fc + hidx;
        wf0 = pf[0]; wf1 = pf[TH]; wf2 = pf[2*TH]; wf3 = pf[3*TH];
    }

    // x staging: stage x(0) into buf 0, prefetch x(1)
    float xreg = 0.f;
    int   s_cc = 0;
    const float* s_ptr = nullptr;
    if (isSX) {
        s_cc  = j - 128;
        s_ptr = g_xT + r0 * C_IN + s_cc;
        ((float*)&xXs[0][s_cc >> 1])[s_cc & 1] = s_ptr[0];
        xreg = s_ptr[BC];
    } else if (isSY) {
        s_cc  = j - 160;
        s_ptr = g_xT + (r0 + 1) * C_IN + s_cc;
        ((float*)&xYs[0][s_cc >> 1])[s_cc & 1] = s_ptr[0];
        xreg = s_ptr[BC];
    }
    __syncthreads();

    for (int t = 0; t < T_LEN; t++) {
        const int buf = t & 1;

        // ================= I1: gates_X(t) + state_Y(t-1) =================
        {
            ull a0 = pack2f(bias, 0.f), a1 = 0ull;
            const ulonglong2* hp = reinterpret_cast<const ulonglong2*>(hX);
#pragma unroll
            for (int k = 0; k < 16; k++) {
                ulonglong2 hA = hp[k];
                ffma2(a0, whhp[2*k],     hA.x);
                ffma2(a1, whhp[2*k + 1], hA.y);
            }
            const ulonglong2* xp = reinterpret_cast<const ulonglong2*>(xXs[buf]);
#pragma unroll
            for (int c = 0; c < 5; c++) {
                ulonglong2 xA = xp[c];
                ffma2(a0, wihp[2*c],     xA.x);
                ffma2(a1, wihp[2*c + 1], xA.y);
            }
            ffma2(a0, wihp[10], xXs[buf][10]);

            // state_Y(t-1): consumes gY(t-1), publishes hY(t-1)
            if (isBY && t > 0) {
                float i_ = gY[hidx];
                float f_ = gY[ 64 + hidx];
                float g_ = gY[128 + hidx];
                float o_ = gY[192 + hidx];
                c_state = fmaf(f_, c_state, i_ * g_);
                float h = o_ * tanh_fast(c_state);
                ((float*)hY)[hidx] = h;        // publish first
                p0 = fmaf(h, wf0, p0); p1 = fmaf(h, wf1, p1);
                p2 = fmaf(h, wf2, p2); p3 = fmaf(h, wf3, p3);
                const float* pfn = W_fc + hidx + t * H_SZ;   // wf(t) for next use
                wf0 = pfn[0]; wf1 = pfn[TH]; wf2 = pfn[2*TH]; wf3 = pfn[3*TH];
            }
            // stage x_Y(t+1) into alt buffer, prefetch x_Y(t+2)
            if (isSY) {
                ((float*)&xYs[buf ^ 1][s_cc >> 1])[s_cc & 1] = xreg;
                int tn = (t + 2 < T_LEN) ? t + 2 : t;
                xreg = s_ptr[tn * BC];
            }

            float e0, o0;
            unpack2(add2(a0, a1), e0, o0);
            gX[j] = fmaf(nl_sc, tanh_fast(nl_pre * (e0 + o0)), nl_off);
        }
        __syncthreads();

        // ================= I2: gates_Y(t) + state_X(t) =================
        {
            ull a0 = pack2f(bias, 0.f), a1 = 0ull;
            const ulonglong2* hp = reinterpret_cast<const ulonglong2*>(hY);
#pragma unroll
            for (int k = 0; k < 16; k++) {
                ulonglong2 hA = hp[k];
                ffma2(a0, whhp[2*k],     hA.x);
                ffma2(a1, whhp[2*k + 1], hA.y);
            }
            const ulonglong2* xp = reinterpret_cast<const ulonglong2*>(xYs[buf]);
#pragma unroll
            for (int c = 0; c < 5; c++) {
                ulonglong2 xA = xp[c];
                ffma2(a0, wihp[2*c],     xA.x);
                ffma2(a1, wihp[2*c + 1], xA.y);
            }
            ffma2(a0, wihp[10], xYs[buf][10]);

            // state_X(t): consumes gX(t), publishes hX(t)
            if (isBX) {
                float i_ = gX[hidx];
                float f_ = gX[ 64 + hidx];
                float g_ = gX[128 + hidx];
                float o_ = gX[192 + hidx];
                c_state = fmaf(f_, c_state, i_ * g_);
                float h = o_ * tanh_fast(c_state);
                ((float*)hX)[hidx] = h;        // publish first
                p0 = fmaf(h, wf0, p0); p1 = fmaf(h, wf1, p1);
                p2 = fmaf(h, wf2, p2); p3 = fmaf(h, wf3, p3);
                int tn = (t + 1 < T_LEN) ? t + 1 : t;
                const float* pfn = W_fc + hidx + tn * H_SZ;
                wf0 = pfn[0]; wf1 = pfn[TH]; wf2 = pfn[2*TH]; wf3 = pfn[3*TH];
            }
            // stage x_X(t+1) into alt buffer, prefetch x_X(t+2)
            if (isSX) {
                ((float*)&xXs[buf ^ 1][s_cc >> 1])[s_cc & 1] = xreg;
                int tn = (t + 2 < T_LEN) ? t + 2 : t;
                xreg = s_ptr[tn * BC];
            }

            float e0, o0;
            unpack2(add2(a0, a1), e0, o0);
            gY[j] = fmaf(nl_sc, tanh_fast(nl_pre * (e0 + o0)), nl_off);
        }
        __syncthreads();
    }

    // epilogue: state_Y(T-1) (no h publish needed)
    if (isBY) {
        float i_ = gY[hidx];
        float f_ = gY[ 64 + hidx];
        float g_ = gY[128 + hidx];
        float o_ = gY[192 + hidx];
        c_state = fmaf(f_, c_state, i_ * g_);
        float h = o_ * tanh_fast(c_state);
        p0 = fmaf(h, wf0, p0); p1 = fmaf(h, wf1, p1);
        p2 = fmaf(h, wf2, p2); p3 = fmaf(h, wf3, p3);
    }

    // ---- FC reduction + softmax ----
    if (j < 128) {
        int row = j >> 6;   // 0 = X, 1 = Y
        red[(row * 4 + 0) * 64 + hidx] = p0;
        red[(row * 4 + 1) * 64 + hidx] = p1;
        red[(row * 4 + 2) * 64 + hidx] = p2;
        red[(row * 4 + 3) * 64 + hidx] = p3;
    }
    __syncthreads();
    if (j < 8) {
        int rr = j >> 2, nn = j & 3;
        float s = 0.f;
#pragma unroll
        for (int k = 0; k < 64; k++) s += red[(rr * 4 + nn) * 64 + k];
        logits_sh[rr][nn] = s + b_fc[nn];
    }
    __syncthreads();
    if (j < 2) {
        float l0 = logits_sh[j][0], l1 = logits_sh[j][1];
        float l2 = logits_sh[j][2], l3 = logits_sh[j][3];
        float m  = fmaxf(fmaxf(l0, l1), fmaxf(l2, l3));
        float q0 = __expf(l0 - m), q1 = __expf(l1 - m);
        float q2 = __expf(l2 - m), q3 = __expf(l3 - m);
        float inv = 1.f / (q0 + q1 + q2 + q3);
        float* o = out + (r0 + j) * 4;
        o[0] = q0 * inv; o[1] = q1 * inv; o[2] = q2 * inv; o[3] = q3 * inv;
    }
}

// ---------------------------------------------------------------------------
extern "C" void kernel_launch(void* const* d_in, const int* in_sizes, int n_in,
                              void* d_out, int out_size) {
    const float* x    = (const float*)d_in[0];
    const float* W_ih = (const float*)d_in[1];
    const float* W_hh = (const float*)d_in[2];
    const float* b_ih = (const float*)d_in[3];
    const float* b_hh = (const float*)d_in[4];
    const float* W_fc = (const float*)d_in[5];
    const float* b_fc = (const float*)d_in[6];
    float* out = (float*)d_out;

    dim3 tgrid((T_LEN + 31) / 32, BC / 32);
    dim3 tblk(32, 8);
    transpose_kernel<<<tgrid, tblk>>>(x);

    lstm_fused<<<B_SZ / 2, 256>>>(W_ih, W_hh, b_ih, b_hh, W_fc, b_fc, out);
}